// round 15
// baseline (speedup 1.0000x reference)
#include <cuda_runtime.h>
#include <cuda_bf16.h>
#include <math.h>

#define TT 1024
#define NB 256
#define DX 16
#define DU 16
#define DA 32
#define NT 256
#define CH 64
#define SLABS 8
#define CONV_EPS 1e-5f

__device__ __align__(16) float g_LpF[NB * 256];
__device__ __align__(16) float g_LtF[NB * 256];
__device__ __align__(16) float g_K[NB * 512];
__device__ float g_muc[NB * 16];
__device__ int g_tconv[NB];

// in-warp unrolled 16x16 Gauss-Jordan inverse (lane j owns column j&15).
__device__ __forceinline__ void inv16_warp(float Sc[DX], int lane)
{
    const unsigned FULL = 0xffffffffu;
    #pragma unroll
    for (int k = 0; k < DX; ++k) {
        float piv = __shfl_sync(FULL, Sc[k], k);
        float d   = __frcp_rn(piv);
        float rjj = (lane == k) ? d : Sc[k] * d;
        #pragma unroll
        for (int i = 0; i < DX; ++i) {
            if (i == k) continue;
            float cki  = __shfl_sync(FULL, Sc[i], k);
            float base = (lane == k) ? 0.f : Sc[i];
            Sc[i] = fmaf(-cki, rjj, base);
        }
        Sc[k] = rjj;
    }
}

// ==================== Phase A: exact Kalman steps (5-barrier pipeline) ============
__global__ __launch_bounds__(NT, 2)
void ldm_phaseA(const float* __restrict__ a_g,
                const float* __restrict__ u_g,
                const float* __restrict__ mask_g,
                const float* __restrict__ A_g,
                const float* __restrict__ B_g,
                const float* __restrict__ C_g,
                const float* __restrict__ mu0_g,
                const float* __restrict__ Lam0_g,
                const float* __restrict__ Wl_g,
                const float* __restrict__ Rl_g,
                float* __restrict__ out)
{
    const int b   = blockIdx.x;
    const int tid = threadIdx.x;

    float* mu_pred_out = out;
    float* mu_t_out    = out + (size_t)TT * NB * DX;
    float* Lp_out      = out + (size_t)2 * TT * NB * DX;
    float* Lt_out      = Lp_out + (size_t)TT * NB * 256;

    __shared__ float Cs[DA * 17];
    __shared__ float Ct2[DX * 33];
    __shared__ float As[DX * 17];
    __shared__ float Bs[DX * 17];
    __shared__ float Us[DX * 17];
    __shared__ float Pbuf[2][DX * 17];
    __shared__ float LTs[DX * 17];
    __shared__ float ALs[DX * 17];
    __shared__ float TIs[DX * 17];
    __shared__ float Vs[DX * 17];
    __shared__ float APs[DX * 17];
    __shared__ float Wd[DX], Rd[DA];
    __shared__ float sa[2][DA], su[2][DU], smv2[2];
    __shared__ float ca2[2][DX];
    __shared__ float cr[DX];
    __shared__ float muS[2][DX], mut[DX];
    __shared__ float wmax8[NT / 32];
    __shared__ int   lastChange, convFlag;

    for (int i = tid; i < DA * DX; i += NT) Cs[(i / DX) * 17 + (i % DX)] = C_g[i];
    for (int i = tid; i < DX * DX; i += NT) {
        As[(i / DX) * 17 + (i % DX)]      = A_g[i];
        Pbuf[0][(i / DX) * 17 + (i % DX)] = Lam0_g[i];
    }
    for (int i = tid; i < DX * DU; i += NT) Bs[(i / DU) * 17 + (i % DU)] = B_g[i];
    if (tid < DX) { Wd[tid] = expf(Wl_g[tid]); muS[0][tid] = mu0_g[tid]; }
    if (tid < DA) Rd[tid] = expf(Rl_g[tid]);
    if (tid == 0) { lastChange = 0; convFlag = 0; }
    __syncthreads();

    for (int i = tid; i < DX * DA; i += NT) {
        int x = i >> 5, aa = i & 31;
        Ct2[x * 33 + aa] = Cs[aa * 17 + x] / Rd[aa];
    }
    {
        int lc = 0;
        for (int t = tid + 1; t < TT; t += NT)
            if (mask_g[(size_t)b * TT + t] != mask_g[(size_t)b * TT + t - 1]) lc = t;
        atomicMax(&lastChange, lc);
    }
    __syncthreads();

    const int x16 = tid >> 4, y16 = tid & 15;
    const int lane = tid & 31, wid = tid >> 5;
    const int lj   = lane & 15;

    {
        float s = 0.f;
        #pragma unroll
        for (int aa = 0; aa < DA; ++aa) s += Ct2[x16 * 33 + aa] * Cs[aa * 17 + y16];
        Us[x16 * 17 + y16] = s;
    }
    if (tid < DA) sa[0][tid] = a_g[(size_t)b * TT * DA + tid];
    if (tid >= 64 && tid < 64 + DU) su[0][tid - 64] = u_g[(size_t)b * TT * DU + (tid - 64)];
    if (tid == 96) smv2[0] = mask_g[(size_t)b * TT];
    __syncthreads();

    float Uic[DX];
    if (wid == 0) {
        #pragma unroll
        for (int i = 0; i < DX; ++i) Uic[i] = Us[i * 17 + lj];
        inv16_warp(Uic, lj);
    }
    if (tid >= 32 && tid < 32 + DX) {
        int x = tid - 32;
        float s = 0.f;
        #pragma unroll
        for (int aa = 0; aa < DA; ++aa) s += Ct2[x * 33 + aa] * sa[0][aa];
        ca2[0][x] = s;
    }
    {
        float s = 0.f;
        #pragma unroll
        for (int z = 0; z < DX; ++z) s += As[x16 * 17 + z] * Pbuf[0][z * 17 + y16];
        APs[x16 * 17 + y16] = s;
    }
    __syncthreads();

    float* Pcur  = Pbuf[0];
    float* Pnext = Pbuf[1];
    int tconv = TT;
    float mfreeze = 1.f;

    #pragma unroll 1
    for (int t = 0; t < TT; ++t) {
        const int p = t & 1;
        const float m = smv2[p];
        const bool doUpd = (m != 0.0f);

        if (doUpd && wid == 0) {
            float Tc[DX];
            #pragma unroll
            for (int i = 0; i < DX; ++i) Tc[i] = Pcur[i * 17 + lj] + Uic[i];
            inv16_warp(Tc, lj);
            if (lane < DX) {
                #pragma unroll
                for (int i = 0; i < DX; ++i) TIs[i * 17 + lj] = Tc[i];
            }
        }
        if (doUpd && tid >= 32 && tid < 32 + DX) {
            int x = tid - 32;
            float s = m * ca2[p][x];
            #pragma unroll
            for (int y = 0; y < DX; ++y) s -= Us[x * 17 + y] * muS[p][y];
            cr[x] = s;
        }
        if (t > 0 && tid >= 96 && tid < 96 + DX)
            mu_pred_out[((size_t)(t - 1) * NB + b) * DX + (tid - 96)] = muS[p][tid - 96];
        if (t + 1 < TT) {
            const size_t base = (size_t)b * TT + t + 1;
            if (tid >= 192 && tid < 192 + DA) sa[1 - p][tid - 192] = a_g[base * DA + tid - 192];
            if (tid >= 224 && tid < 224 + DU)
                su[1 - p][tid - 224] = (t + 1 == TT - 1) ? 0.f : u_g[base * DU + tid - 224];
            if (tid == 240) smv2[1 - p] = mask_g[base];
        }
        __syncthreads();   // B1

        if (doUpd) {
            float s = 0.f;
            #pragma unroll
            for (int z = 0; z < DX; ++z) s += TIs[x16 * 17 + z] * Pcur[z * 17 + y16];
            Vs[x16 * 17 + y16] = s;
        }
        __syncthreads();   // B2

        {
            float sl = Pcur[x16 * 17 + y16];
            float sA = APs[x16 * 17 + y16];
            if (doUpd) {
                #pragma unroll
                for (int z = 0; z < DX; ++z) {
                    float v = Vs[z * 17 + y16];
                    sl -= Pcur[x16 * 17 + z] * v;
                    sA -= APs[x16 * 17 + z] * v;
                }
            }
            LTs[x16 * 17 + y16] = sl;
            ALs[x16 * 17 + y16] = sA;
        }
        __syncthreads();   // B3

        float mydiff;
        {
            float s = (x16 == y16) ? Wd[x16] : 0.f;
            #pragma unroll
            for (int z = 0; z < DX; ++z) s += ALs[x16 * 17 + z] * As[y16 * 17 + z];
            Pnext[x16 * 17 + y16] = s;
            mydiff = fabsf(s - Pcur[x16 * 17 + y16]);
        }
        #pragma unroll
        for (int o = 16; o; o >>= 1)
            mydiff = fmaxf(mydiff, __shfl_xor_sync(0xffffffffu, mydiff, o));
        if (lane == 0) wmax8[wid] = mydiff;
        if (tid < DX) {
            float s = muS[p][tid];
            if (doUpd) {
                float acc = 0.f;
                #pragma unroll
                for (int j = 0; j < DX; ++j) acc += LTs[tid * 17 + j] * cr[j];
                s = fmaf(m, acc, s);
            }
            mut[tid] = s;
        }
        if (t + 1 < TT && tid >= 208 && tid < 208 + DX) {
            int x = tid - 208;
            float s = 0.f;
            #pragma unroll
            for (int aa = 0; aa < DA; ++aa) s += Ct2[x * 33 + aa] * sa[1 - p][aa];
            ca2[1 - p][x] = s;
        }
        __syncthreads();   // B4

        {
            float s = 0.f;
            #pragma unroll
            for (int z = 0; z < DX; ++z) s += As[x16 * 17 + z] * Pnext[z * 17 + y16];
            APs[x16 * 17 + y16] = s;
        }
        if (tid < DX) {
            float s = 0.f;
            #pragma unroll
            for (int y = 0; y < DX; ++y) s += As[tid * 17 + y] * mut[y];
            #pragma unroll
            for (int uu = 0; uu < DU; ++uu) s += Bs[tid * 17 + uu] * su[p][uu];
            muS[1 - p][tid] = s;
        }
        {
            size_t ob = (size_t)t * NB + b;
            Lp_out[ob * 256 + tid] = Pnext[x16 * 17 + y16];
            Lt_out[ob * 256 + tid] = LTs[x16 * 17 + y16];
            if (tid >= 32 && tid < 32 + DX)
                mu_t_out[ob * DX + (tid - 32)] = mut[tid - 32];
        }
        if (tid == 255) {
            float md = wmax8[0];
            #pragma unroll
            for (int w = 1; w < NT / 32; ++w) md = fmaxf(md, wmax8[w]);
            convFlag = (md < CONV_EPS && t >= lastChange &&
                        (t + 1) < TT && (((t + 1) & 3) == 0)) ? 1 : 0;
        }
        __syncthreads();   // B5

        { float* tp = Pcur; Pcur = Pnext; Pnext = tp; }
        if (convFlag) { tconv = t + 1; mfreeze = m; break; }
    }

    {
        int last = (tconv < TT ? tconv : TT) - 1;
        if (tid < DX)
            mu_pred_out[((size_t)last * NB + b) * DX + tid] = muS[(last + 1) & 1][tid];
    }

    if (tid == 0) g_tconv[b] = tconv;
    if (tconv >= TT) return;

    g_LpF[b * 256 + tid] = Pcur[x16 * 17 + y16];
    g_LtF[b * 256 + tid] = LTs[x16 * 17 + y16];
    #pragma unroll
    for (int q = 0; q < 2; ++q) {
        int e = tid + q * NT, x = e >> 5, aa = e & 31;
        float s = 0.f;
        #pragma unroll
        for (int y = 0; y < DX; ++y) s += LTs[x * 17 + y] * Ct2[y * 33 + aa];
        g_K[b * 512 + x * 32 + aa] = mfreeze * s;
    }
    if (tid < DX) g_muc[b * 16 + tid] = muS[tconv & 1][tid];
}

// ==================== Phase B: frozen-gain mu recurrence (standalone) ====
__global__ __launch_bounds__(NT, 2)
void ldm_phaseB(const float* __restrict__ a_g,
                const float* __restrict__ u_g,
                const float* __restrict__ mask_g,
                const float* __restrict__ A_g,
                const float* __restrict__ B_g,
                const float* __restrict__ C_g,
                float* __restrict__ out)
{
    const int b = blockIdx.x, tid = threadIdx.x;
    float* mu_pred_out = out;
    float* mu_t_out    = out + (size_t)TT * NB * DX;

    const int tconv = g_tconv[b];
    if (tconv >= TT) return;

    __shared__ float As[DX * 17], Bs[DX * 17], Cs[DA * 17], Ks[DX * 33];
    __shared__ float FM[DX * 17], MM[DX * 17], M2s[DX * 17], M3s[DX * 17], M4s[DX * 17];
    __shared__ __align__(16) float AB[CH * DA];
    __shared__ __align__(16) float UB[CH * DU];
    __shared__ float GB[CH * 17], HB[CH * 17];
    __shared__ float S1[(CH / 4) * 17], S2[(CH / 4) * 17], HH[(CH / 4) * 17];
    __shared__ float CHK[(CH / 4 + 1) * 17];
    __shared__ float PBF[CH * 17];
    __shared__ float MB[CH];

    const int x16 = tid >> 4, y16 = tid & 15;
    const int lane = tid & 31, wid = tid >> 5;

    for (int i = tid; i < DA * DX; i += NT) Cs[(i / DX) * 17 + (i % DX)] = C_g[i];
    for (int i = tid; i < DX * DX; i += NT) As[(i / DX) * 17 + (i % DX)] = A_g[i];
    for (int i = tid; i < DX * DU; i += NT) Bs[(i / DU) * 17 + (i % DU)] = B_g[i];
    #pragma unroll
    for (int q = 0; q < 2; ++q) {
        int e = tid + q * NT;
        Ks[(e >> 5) * 33 + (e & 31)] = g_K[b * 512 + e];
    }
    __syncthreads();

    {
        float s = (x16 == y16) ? 1.f : 0.f;
        #pragma unroll
        for (int aa = 0; aa < DA; ++aa) s -= Ks[x16 * 33 + aa] * Cs[aa * 17 + y16];
        FM[x16 * 17 + y16] = s;
    }
    __syncthreads();
    {
        float s = 0.f;
        #pragma unroll
        for (int z = 0; z < DX; ++z) s += As[x16 * 17 + z] * FM[z * 17 + y16];
        MM[x16 * 17 + y16] = s;
    }
    __syncthreads();
    {
        float s = 0.f;
        #pragma unroll
        for (int z = 0; z < DX; ++z) s += MM[x16 * 17 + z] * MM[z * 17 + y16];
        M2s[x16 * 17 + y16] = s;
    }
    __syncthreads();
    {
        float s3 = 0.f, s4 = 0.f;
        #pragma unroll
        for (int z = 0; z < DX; ++z) {
            s3 += M2s[x16 * 17 + z] * MM[z * 17 + y16];
            s4 += M2s[x16 * 17 + z] * M2s[z * 17 + y16];
        }
        M3s[x16 * 17 + y16] = s3;
        M4s[x16 * 17 + y16] = s4;
    }
    __syncthreads();

    float M4row[DX], muv = 0.f;
    if (wid == 0) {
        if (lane < DX) {
            #pragma unroll
            for (int j = 0; j < DX; ++j) M4row[j] = M4s[lane * 17 + j];
            muv = g_muc[b * 16 + lane];
        } else {
            #pragma unroll
            for (int j = 0; j < DX; ++j) M4row[j] = 0.f;
        }
    }

    for (int t0 = tconv; t0 < TT; t0 += CH) {
        const int L   = min(CH, TT - t0);
        const int NGl = L >> 2;

        {
            const float4* a4 = (const float4*)(a_g + ((size_t)b * TT + t0) * DA);
            for (int i2 = tid; i2 < L * 8; i2 += NT) ((float4*)AB)[i2] = a4[i2];
            const float4* u4 = (const float4*)(u_g + ((size_t)b * TT + t0) * DU);
            for (int i2 = tid; i2 < L * 4; i2 += NT) ((float4*)UB)[i2] = u4[i2];
            if (tid < L) MB[tid] = mask_g[(size_t)b * TT + t0 + tid];
        }
        __syncthreads();

        for (int e = tid; e < L * DX; e += NT) {
            int s = e >> 4, x = e & 15;
            const float* ar = AB + s * DA;
            float g = 0.f;
            #pragma unroll
            for (int aa = 0; aa < DA; ++aa) g += Ks[x * 33 + aa] * ar[aa];
            GB[s * 17 + x] = MB[s] * g;
        }
        __syncthreads();

        for (int e = tid; e < L * DX; e += NT) {
            int s = e >> 4, x = e & 15;
            float h = 0.f;
            #pragma unroll
            for (int z = 0; z < DX; ++z) h += As[x * 17 + z] * GB[s * 17 + z];
            if (t0 + s != TT - 1) {
                const float* ur = UB + s * DU;
                #pragma unroll
                for (int uu = 0; uu < DU; ++uu) h += Bs[x * 17 + uu] * ur[uu];
            }
            HB[s * 17 + x] = h;
        }
        __syncthreads();

        for (int e = tid; e < NGl * DX; e += NT) {
            int q = e >> 4, x = e & 15;
            const float* h0 = HB + (4 * q) * 17;
            float s1 = h0[17 + x], s2 = h0[34 + x], hh = h0[51 + x];
            #pragma unroll
            for (int j = 0; j < DX; ++j) {
                float h0j = h0[j], h1j = h0[17 + j], h2j = h0[34 + j];
                float mj  = MM[x * 17 + j];
                float m2j = M2s[x * 17 + j];
                s1 = fmaf(mj,  h0j, s1);
                s2 = fmaf(m2j, h0j, fmaf(mj, h1j, s2));
                hh = fmaf(M3s[x * 17 + j], h0j, fmaf(m2j, h1j, fmaf(mj, h2j, hh)));
            }
            S1[q * 17 + x] = s1;
            S2[q * 17 + x] = s2;
            HH[q * 17 + x] = hh;
        }
        __syncthreads();

        if (wid == 0) {
            #pragma unroll 1
            for (int q = 0; q < NGl; ++q) {
                float nm = (lane < DX) ? HH[q * 17 + lane] : 0.f;
                if (lane < DX) CHK[q * 17 + lane] = muv;
                float a0 = nm, a1 = 0.f;
                #pragma unroll
                for (int j = 0; j < DX; j += 2) {
                    float m0 = __shfl_sync(0xffffffffu, muv, j);
                    float m1 = __shfl_sync(0xffffffffu, muv, j + 1);
                    a0 = fmaf(M4row[j],     m0, a0);
                    a1 = fmaf(M4row[j + 1], m1, a1);
                }
                muv = a0 + a1;
            }
            if (lane < DX) CHK[NGl * 17 + lane] = muv;
        }
        __syncthreads();

        for (int e = tid; e < L * DX; e += NT) {
            int s = e >> 4, x = e & 15, q = s >> 2, r = s & 3;
            float pv;
            if (r == 0) {
                pv = CHK[q * 17 + x];
            } else {
                const float* Mr = (r == 1) ? MM : (r == 2) ? M2s : M3s;
                pv = (r == 1) ? HB[(4 * q) * 17 + x]
                   : (r == 2) ? S1[q * 17 + x] : S2[q * 17 + x];
                #pragma unroll
                for (int j = 0; j < DX; ++j) pv = fmaf(Mr[x * 17 + j], CHK[q * 17 + j], pv);
            }
            PBF[s * 17 + x] = pv;
        }
        __syncthreads();

        for (int e = tid; e < L * DX; e += NT) {
            int s = e >> 4, x = e & 15;
            int t = t0 + s;
            float mt = GB[s * 17 + x];
            #pragma unroll
            for (int j = 0; j < DX; ++j) mt = fmaf(FM[x * 17 + j], PBF[s * 17 + j], mt);
            float mpn = (s + 1 < L) ? PBF[(s + 1) * 17 + x] : CHK[NGl * 17 + x];
            size_t ob = (size_t)t * NB + b;
            mu_t_out[ob * DX + x]    = mt;
            mu_pred_out[ob * DX + x] = mpn;
        }
        __syncthreads();
    }
}

// ==================== Lambda fill at DRAM roofline (plain stores) ====================
__global__ __launch_bounds__(NT)
void ldm_fill(float* __restrict__ out)
{
    const int b = blockIdx.x, slab = blockIdx.y, tid = threadIdx.x;
    float* Lp_out = out + (size_t)2 * TT * NB * DX;
    float* Lt_out = Lp_out + (size_t)TT * NB * 256;

    const int tb0 = slab * (TT / SLABS);
    const int tb1 = tb0 + (TT / SLABS);
    const int tc  = g_tconv[b];
    const int ts  = tc > tb0 ? tc : tb0;
    if (ts >= tb1) return;

    const int r   = tid & 127;
    const int rr2 = r & 63;
    const float4 val = (r < 64) ? ((const float4*)g_LpF)[b * 64 + rr2]
                                : ((const float4*)g_LtF)[b * 64 + rr2];
    float4* dst = (float4*)((r < 64) ? Lp_out : Lt_out);

    const int total = (tb1 - ts) * 128;
    for (int idx = tid; idx < total; idx += NT) {
        int t = ts + (idx >> 7);
        dst[((size_t)t * NB + b) * 64 + rr2] = val;
    }
}

extern "C" void kernel_launch(void* const* d_in, const int* in_sizes, int n_in,
                              void* d_out, int out_size)
{
    (void)in_sizes; (void)n_in; (void)out_size;

    // Forked graph, with phaseB created FIRST so its 256 fat blocks launch into an
    // empty machine; the fill's 2048 lean blocks (own 30-reg allocation) then pack
    // into the remaining registers and run concurrently.
    cudaStream_t s2;
    cudaStreamCreateWithFlags(&s2, cudaStreamNonBlocking);
    cudaEvent_t evFork, evJoin;
    cudaEventCreateWithFlags(&evFork, cudaEventDisableTiming);
    cudaEventCreateWithFlags(&evJoin, cudaEventDisableTiming);

    ldm_phaseA<<<NB, NT>>>(
        (const float*)d_in[0], (const float*)d_in[1], (const float*)d_in[2],
        (const float*)d_in[3], (const float*)d_in[4], (const float*)d_in[5],
        (const float*)d_in[6], (const float*)d_in[7], (const float*)d_in[8],
        (const float*)d_in[9], (float*)d_out);

    cudaEventRecord(evFork, 0);               // fork after phaseA
    cudaStreamWaitEvent(s2, evFork, 0);

    ldm_phaseB<<<NB, NT>>>(                   // legacy stream — created/launched first
        (const float*)d_in[0], (const float*)d_in[1], (const float*)d_in[2],
        (const float*)d_in[3], (const float*)d_in[4], (const float*)d_in[5],
        (float*)d_out);

    ldm_fill<<<dim3(NB, SLABS), NT, 0, s2>>>((float*)d_out);

    cudaEventRecord(evJoin, s2);              // join fill back into legacy stream
    cudaStreamWaitEvent((cudaStream_t)0, evJoin, 0);
}

// round 16
// speedup vs baseline: 1.0079x; 1.0079x over previous
#include <cuda_runtime.h>
#include <cuda_bf16.h>
#include <math.h>

#define TT 1024
#define NB 256
#define DX 16
#define DU 16
#define DA 32
#define NT 256
#define CH 64
#define SLABS 8
#define CONV_EPS 1e-5f

__device__ __align__(16) float g_LpF[NB * 256];
__device__ __align__(16) float g_LtF[NB * 256];
__device__ __align__(16) float g_K[NB * 512];
__device__ float g_muc[NB * 16];
__device__ int g_tconv[NB];

// in-warp unrolled 16x16 Gauss-Jordan inverse (lane j owns column j&15).
__device__ __forceinline__ void inv16_warp(float Sc[DX], int lane)
{
    const unsigned FULL = 0xffffffffu;
    #pragma unroll
    for (int k = 0; k < DX; ++k) {
        float piv = __shfl_sync(FULL, Sc[k], k);
        float d   = __frcp_rn(piv);
        float rjj = (lane == k) ? d : Sc[k] * d;
        #pragma unroll
        for (int i = 0; i < DX; ++i) {
            if (i == k) continue;
            float cki  = __shfl_sync(FULL, Sc[i], k);
            float base = (lane == k) ? 0.f : Sc[i];
            Sc[i] = fmaf(-cki, rjj, base);
        }
        Sc[k] = rjj;
    }
}

// ==================== Phase A: exact Kalman steps until freeze (R11 verbatim) =====
__global__ __launch_bounds__(NT, 2)
void ldm_phaseA(const float* __restrict__ a_g,
                const float* __restrict__ u_g,
                const float* __restrict__ mask_g,
                const float* __restrict__ A_g,
                const float* __restrict__ B_g,
                const float* __restrict__ C_g,
                const float* __restrict__ mu0_g,
                const float* __restrict__ Lam0_g,
                const float* __restrict__ Wl_g,
                const float* __restrict__ Rl_g,
                float* __restrict__ out)
{
    const int b   = blockIdx.x;
    const int tid = threadIdx.x;

    float* mu_pred_out = out;
    float* mu_t_out    = out + (size_t)TT * NB * DX;
    float* Lp_out      = out + (size_t)2 * TT * NB * DX;
    float* Lt_out      = Lp_out + (size_t)TT * NB * 256;

    __shared__ float Cs[DA * 17];
    __shared__ float Ct2[DX * 33];
    __shared__ float As[DX * 17];
    __shared__ float Bs[DX * 17];
    __shared__ float Us[DX * 17];
    __shared__ float Pbuf[2][DX * 17];
    __shared__ float LTs[DX * 17];
    __shared__ float ALs[DX * 17];
    __shared__ float TIs[DX * 17];
    __shared__ float Vs[DX * 17];
    __shared__ float Wd[DX], Rd[DA];
    __shared__ float sa[2][DA], su[2][DU], smv2[2];
    __shared__ float rr[DA], cr[DX];
    __shared__ float muS[2][DX], mut[DX];
    __shared__ float wmax8[NT / 32];
    __shared__ int   lastChange, convFlag;

    for (int i = tid; i < DA * DX; i += NT) Cs[(i / DX) * 17 + (i % DX)] = C_g[i];
    for (int i = tid; i < DX * DX; i += NT) {
        As[(i / DX) * 17 + (i % DX)]      = A_g[i];
        Pbuf[0][(i / DX) * 17 + (i % DX)] = Lam0_g[i];
    }
    for (int i = tid; i < DX * DU; i += NT) Bs[(i / DU) * 17 + (i % DU)] = B_g[i];
    if (tid < DX) { Wd[tid] = expf(Wl_g[tid]); muS[0][tid] = mu0_g[tid]; }
    if (tid < DA) Rd[tid] = expf(Rl_g[tid]);
    if (tid == 0) { lastChange = 0; convFlag = 0; }
    __syncthreads();

    for (int i = tid; i < DX * DA; i += NT) {
        int x = i >> 5, aa = i & 31;
        Ct2[x * 33 + aa] = Cs[aa * 17 + x] / Rd[aa];
    }
    {
        int lc = 0;
        for (int t = tid + 1; t < TT; t += NT)
            if (mask_g[(size_t)b * TT + t] != mask_g[(size_t)b * TT + t - 1]) lc = t;
        atomicMax(&lastChange, lc);
    }
    __syncthreads();

    const int x16 = tid >> 4, y16 = tid & 15;
    const int lane = tid & 31, wid = tid >> 5;
    const int lj   = lane & 15;

    {
        float s = 0.f;
        #pragma unroll
        for (int aa = 0; aa < DA; ++aa) s += Ct2[x16 * 33 + aa] * Cs[aa * 17 + y16];
        Us[x16 * 17 + y16] = s;
    }
    if (tid < DA) sa[0][tid] = a_g[(size_t)b * TT * DA + tid];
    if (tid >= 64 && tid < 64 + DU) su[0][tid - 64] = u_g[(size_t)b * TT * DU + (tid - 64)];
    if (tid == 96) smv2[0] = mask_g[(size_t)b * TT];
    if (tid >= 128 && tid < 128 + DA) {
        int aa = tid - 128;
        float s = 0.f;
        #pragma unroll
        for (int y = 0; y < DX; ++y) s += Cs[aa * 17 + y] * muS[0][y];
        rr[aa] = s;
    }
    __syncthreads();

    float Uic[DX];
    if (wid == 0) {
        #pragma unroll
        for (int i = 0; i < DX; ++i) Uic[i] = Us[i * 17 + lj];
        inv16_warp(Uic, lj);
    }

    float* Pcur  = Pbuf[0];
    float* Pnext = Pbuf[1];
    int tconv = TT;
    float mfreeze = 1.f;

    #pragma unroll 1
    for (int t = 0; t < TT; ++t) {
        const int p = t & 1;
        const float m = smv2[p];
        const bool doUpd = (m != 0.0f);

        if (doUpd && wid == 0) {
            float Tc[DX];
            #pragma unroll
            for (int i = 0; i < DX; ++i) Tc[i] = Pcur[i * 17 + lj] + Uic[i];
            inv16_warp(Tc, lj);
            if (lane < DX) {
                #pragma unroll
                for (int i = 0; i < DX; ++i) TIs[i * 17 + lj] = Tc[i];
            }
        }
        if (doUpd && tid >= 64 && tid < 64 + DX) {
            int x = tid - 64;
            float s = 0.f;
            #pragma unroll
            for (int aa = 0; aa < DA; ++aa)
                s += Ct2[x * 33 + aa] * (m * sa[p][aa] - rr[aa]);
            cr[x] = s;
        }
        if (t + 1 < TT) {
            const size_t base = (size_t)b * TT + t + 1;
            if (tid >= 192 && tid < 192 + DA) sa[1 - p][tid - 192] = a_g[base * DA + tid - 192];
            if (tid >= 224 && tid < 224 + DU)
                su[1 - p][tid - 224] = (t + 1 == TT - 1) ? 0.f : u_g[base * DU + tid - 224];
            if (tid == 240) smv2[1 - p] = mask_g[base];
        }
        __syncthreads();

        if (doUpd) {
            float s = 0.f;
            #pragma unroll
            for (int z = 0; z < DX; ++z) s += TIs[x16 * 17 + z] * Pcur[z * 17 + y16];
            Vs[x16 * 17 + y16] = s;
        }
        __syncthreads();

        {
            float s = Pcur[x16 * 17 + y16];
            if (doUpd) {
                #pragma unroll
                for (int z = 0; z < DX; ++z) s -= Pcur[x16 * 17 + z] * Vs[z * 17 + y16];
            }
            LTs[x16 * 17 + y16] = s;
        }
        __syncthreads();

        {
            float s = 0.f;
            #pragma unroll
            for (int z = 0; z < DX; ++z) s += As[x16 * 17 + z] * LTs[z * 17 + y16];
            ALs[x16 * 17 + y16] = s;
        }
        if (tid < DX) {
            float s = muS[p][tid];
            if (doUpd) {
                float acc = 0.f;
                #pragma unroll
                for (int j = 0; j < DX; ++j) acc += LTs[tid * 17 + j] * cr[j];
                s = fmaf(m, acc, s);
            }
            mut[tid] = s;
        }
        __syncthreads();

        float mydiff;
        {
            float s = (x16 == y16) ? Wd[x16] : 0.f;
            #pragma unroll
            for (int z = 0; z < DX; ++z) s += ALs[x16 * 17 + z] * As[y16 * 17 + z];
            Pnext[x16 * 17 + y16] = s;
            mydiff = fabsf(s - Pcur[x16 * 17 + y16]);
        }
        #pragma unroll
        for (int o = 16; o; o >>= 1)
            mydiff = fmaxf(mydiff, __shfl_xor_sync(0xffffffffu, mydiff, o));
        if (lane == 0) wmax8[wid] = mydiff;
        if (tid < DX) {
            float s = 0.f;
            #pragma unroll
            for (int y = 0; y < DX; ++y) s += As[tid * 17 + y] * mut[y];
            #pragma unroll
            for (int uu = 0; uu < DU; ++uu) s += Bs[tid * 17 + uu] * su[p][uu];
            muS[1 - p][tid] = s;
        }
        __syncthreads();

        {
            size_t ob = (size_t)t * NB + b;
            Lp_out[ob * 256 + tid] = Pnext[x16 * 17 + y16];
            Lt_out[ob * 256 + tid] = LTs[x16 * 17 + y16];
            if (tid < DX) mu_t_out[ob * DX + tid] = mut[tid];
            else if (tid < 2 * DX) mu_pred_out[ob * DX + tid - DX] = muS[1 - p][tid - DX];
        }
        if (tid >= 128 && tid < 128 + DA) {
            int aa = tid - 128;
            float s = 0.f;
            #pragma unroll
            for (int y = 0; y < DX; ++y) s += Cs[aa * 17 + y] * muS[1 - p][y];
            rr[aa] = s;
        }
        if (tid == 255) {
            float md = wmax8[0];
            #pragma unroll
            for (int w = 1; w < NT / 32; ++w) md = fmaxf(md, wmax8[w]);
            convFlag = (md < CONV_EPS && t >= lastChange &&
                        (t + 1) < TT && (((t + 1) & 3) == 0)) ? 1 : 0;
        }
        __syncthreads();

        { float* tp = Pcur; Pcur = Pnext; Pnext = tp; }
        if (convFlag) { tconv = t + 1; mfreeze = m; break; }
    }

    if (tid == 0) g_tconv[b] = tconv;
    if (tconv >= TT) return;

    g_LpF[b * 256 + tid] = Pcur[x16 * 17 + y16];
    g_LtF[b * 256 + tid] = LTs[x16 * 17 + y16];
    #pragma unroll
    for (int q = 0; q < 2; ++q) {
        int e = tid + q * NT, x = e >> 5, aa = e & 31;
        float s = 0.f;
        #pragma unroll
        for (int y = 0; y < DX; ++y) s += LTs[x * 17 + y] * Ct2[y * 33 + aa];
        g_K[b * 512 + x * 32 + aa] = mfreeze * s;
    }
    if (tid < DX) g_muc[b * 16 + tid] = muS[tconv & 1][tid];
}

// ==================== tail: Lambda fill (y>=1) + mu Phase B (y==0), overlapped ====
// Natural register allocation (NO launch-bounds cap). Single change vs the 252.0us
// best: the serial chain reads M^4 from shared (stride-17, conflict-free) instead
// of a 16-register private array, aiming to land naturally at <=64 regs.
__global__ __launch_bounds__(NT)
void ldm_tail(const float* __restrict__ a_g,
              const float* __restrict__ u_g,
              const float* __restrict__ mask_g,
              const float* __restrict__ A_g,
              const float* __restrict__ B_g,
              const float* __restrict__ C_g,
              float* __restrict__ out)
{
    const int b = blockIdx.x, tid = threadIdx.x;
    float* mu_pred_out = out;
    float* mu_t_out    = out + (size_t)TT * NB * DX;
    float* Lp_out      = out + (size_t)2 * TT * NB * DX;
    float* Lt_out      = Lp_out + (size_t)TT * NB * 256;

    if (blockIdx.y > 0) {
        // ---------------- Lambda fill slab: 4x-unrolled independent stores ----
        const int slab = blockIdx.y - 1;
        const int tb0 = slab * (TT / SLABS);
        const int tb1 = tb0 + (TT / SLABS);
        const int tc  = g_tconv[b];
        const int ts  = tc > tb0 ? tc : tb0;
        if (ts >= tb1) return;

        const int r   = tid & 127;
        const int rr2 = r & 63;
        const float4 val = (r < 64) ? ((const float4*)g_LpF)[b * 64 + rr2]
                                    : ((const float4*)g_LtF)[b * 64 + rr2];
        float4* dst = (float4*)((r < 64) ? Lp_out : Lt_out);

        for (int t = ts + (tid >> 7); t < tb1; t += 8) {
            #pragma unroll
            for (int k = 0; k < 4; ++k) {
                int tt = t + 2 * k;
                if (tt < tb1)
                    dst[((size_t)tt * NB + b) * 64 + rr2] = val;
            }
        }
        return;
    }

    // ---------------- Phase B: frozen-gain mu recurrence ----------------
    const int tconv = g_tconv[b];
    if (tconv >= TT) return;

    __shared__ float As[DX * 17], Bs[DX * 17], Cs[DA * 17], Ks[DX * 33];
    __shared__ float FM[DX * 17], MM[DX * 17], M2s[DX * 17], M3s[DX * 17], M4s[DX * 17];
    __shared__ __align__(16) float AB[CH * DA];
    __shared__ __align__(16) float UB[CH * DU];
    __shared__ float GB[CH * 17], HB[CH * 17];
    __shared__ float S1[(CH / 4) * 17], S2[(CH / 4) * 17], HH[(CH / 4) * 17];
    __shared__ float CHK[(CH / 4 + 1) * 17];
    __shared__ float PBF[CH * 17];
    __shared__ float MB[CH];

    const int x16 = tid >> 4, y16 = tid & 15;
    const int lane = tid & 31, wid = tid >> 5;

    for (int i = tid; i < DA * DX; i += NT) Cs[(i / DX) * 17 + (i % DX)] = C_g[i];
    for (int i = tid; i < DX * DX; i += NT) As[(i / DX) * 17 + (i % DX)] = A_g[i];
    for (int i = tid; i < DX * DU; i += NT) Bs[(i / DU) * 17 + (i % DU)] = B_g[i];
    #pragma unroll
    for (int q = 0; q < 2; ++q) {
        int e = tid + q * NT;
        Ks[(e >> 5) * 33 + (e & 31)] = g_K[b * 512 + e];
    }
    __syncthreads();

    {
        float s = (x16 == y16) ? 1.f : 0.f;
        #pragma unroll
        for (int aa = 0; aa < DA; ++aa) s -= Ks[x16 * 33 + aa] * Cs[aa * 17 + y16];
        FM[x16 * 17 + y16] = s;
    }
    __syncthreads();
    {
        float s = 0.f;
        #pragma unroll
        for (int z = 0; z < DX; ++z) s += As[x16 * 17 + z] * FM[z * 17 + y16];
        MM[x16 * 17 + y16] = s;
    }
    __syncthreads();
    {
        float s = 0.f;
        #pragma unroll
        for (int z = 0; z < DX; ++z) s += MM[x16 * 17 + z] * MM[z * 17 + y16];
        M2s[x16 * 17 + y16] = s;
    }
    __syncthreads();
    {
        float s3 = 0.f, s4 = 0.f;
        #pragma unroll
        for (int z = 0; z < DX; ++z) {
            s3 += M2s[x16 * 17 + z] * MM[z * 17 + y16];
            s4 += M2s[x16 * 17 + z] * M2s[z * 17 + y16];
        }
        M3s[x16 * 17 + y16] = s3;
        M4s[x16 * 17 + y16] = s4;
    }
    __syncthreads();

    float muv = 0.f;
    if (wid == 0 && lane < DX) muv = g_muc[b * 16 + lane];

    for (int t0 = tconv; t0 < TT; t0 += CH) {
        const int L   = min(CH, TT - t0);
        const int NGl = L >> 2;

        {
            const float4* a4 = (const float4*)(a_g + ((size_t)b * TT + t0) * DA);
            for (int i2 = tid; i2 < L * 8; i2 += NT) ((float4*)AB)[i2] = a4[i2];
            const float4* u4 = (const float4*)(u_g + ((size_t)b * TT + t0) * DU);
            for (int i2 = tid; i2 < L * 4; i2 += NT) ((float4*)UB)[i2] = u4[i2];
            if (tid < L) MB[tid] = mask_g[(size_t)b * TT + t0 + tid];
        }
        __syncthreads();

        for (int e = tid; e < L * DX; e += NT) {
            int s = e >> 4, x = e & 15;
            const float* ar = AB + s * DA;
            float g = 0.f;
            #pragma unroll
            for (int aa = 0; aa < DA; ++aa) g += Ks[x * 33 + aa] * ar[aa];
            GB[s * 17 + x] = MB[s] * g;
        }
        __syncthreads();

        for (int e = tid; e < L * DX; e += NT) {
            int s = e >> 4, x = e & 15;
            float h = 0.f;
            #pragma unroll
            for (int z = 0; z < DX; ++z) h += As[x * 17 + z] * GB[s * 17 + z];
            if (t0 + s != TT - 1) {
                const float* ur = UB + s * DU;
                #pragma unroll
                for (int uu = 0; uu < DU; ++uu) h += Bs[x * 17 + uu] * ur[uu];
            }
            HB[s * 17 + x] = h;
        }
        __syncthreads();

        for (int e = tid; e < NGl * DX; e += NT) {
            int q = e >> 4, x = e & 15;
            const float* h0 = HB + (4 * q) * 17;
            float s1 = h0[17 + x], s2 = h0[34 + x], hh = h0[51 + x];
            #pragma unroll
            for (int j = 0; j < DX; ++j) {
                float h0j = h0[j], h1j = h0[17 + j], h2j = h0[34 + j];
                float mj  = MM[x * 17 + j];
                float m2j = M2s[x * 17 + j];
                s1 = fmaf(mj,  h0j, s1);
                s2 = fmaf(m2j, h0j, fmaf(mj, h1j, s2));
                hh = fmaf(M3s[x * 17 + j], h0j, fmaf(m2j, h1j, fmaf(mj, h2j, hh)));
            }
            S1[q * 17 + x] = s1;
            S2[q * 17 + x] = s2;
            HH[q * 17 + x] = hh;
        }
        __syncthreads();

        if (wid == 0) {
            const int row = lane & 15;
            #pragma unroll 1
            for (int q = 0; q < NGl; ++q) {
                float nm = (lane < DX) ? HH[q * 17 + lane] : 0.f;
                if (lane < DX) CHK[q * 17 + lane] = muv;
                float a0 = nm, a1 = 0.f;
                #pragma unroll
                for (int j = 0; j < DX; j += 2) {
                    float m0 = __shfl_sync(0xffffffffu, muv, j);
                    float m1 = __shfl_sync(0xffffffffu, muv, j + 1);
                    a0 = fmaf(M4s[row * 17 + j],     m0, a0);
                    a1 = fmaf(M4s[row * 17 + j + 1], m1, a1);
                }
                muv = a0 + a1;
            }
            if (lane < DX) CHK[NGl * 17 + lane] = muv;
        }
        __syncthreads();

        for (int e = tid; e < L * DX; e += NT) {
            int s = e >> 4, x = e & 15, q = s >> 2, r = s & 3;
            float pv;
            if (r == 0) {
                pv = CHK[q * 17 + x];
            } else {
                const float* Mr = (r == 1) ? MM : (r == 2) ? M2s : M3s;
                pv = (r == 1) ? HB[(4 * q) * 17 + x]
                   : (r == 2) ? S1[q * 17 + x] : S2[q * 17 + x];
                #pragma unroll
                for (int j = 0; j < DX; ++j) pv = fmaf(Mr[x * 17 + j], CHK[q * 17 + j], pv);
            }
            PBF[s * 17 + x] = pv;
        }
        __syncthreads();

        for (int e = tid; e < L * DX; e += NT) {
            int s = e >> 4, x = e & 15;
            int t = t0 + s;
            float mt = GB[s * 17 + x];
            #pragma unroll
            for (int j = 0; j < DX; ++j) mt = fmaf(FM[x * 17 + j], PBF[s * 17 + j], mt);
            float mpn = (s + 1 < L) ? PBF[(s + 1) * 17 + x] : CHK[NGl * 17 + x];
            size_t ob = (size_t)t * NB + b;
            mu_t_out[ob * DX + x]    = mt;
            mu_pred_out[ob * DX + x] = mpn;
        }
        __syncthreads();
    }
}

extern "C" void kernel_launch(void* const* d_in, const int* in_sizes, int n_in,
                              void* d_out, int out_size)
{
    (void)in_sizes; (void)n_in; (void)out_size;
    ldm_phaseA<<<NB, NT>>>(
        (const float*)d_in[0], (const float*)d_in[1], (const float*)d_in[2],
        (const float*)d_in[3], (const float*)d_in[4], (const float*)d_in[5],
        (const float*)d_in[6], (const float*)d_in[7], (const float*)d_in[8],
        (const float*)d_in[9], (float*)d_out);
    ldm_tail<<<dim3(NB, SLABS + 1), NT>>>(
        (const float*)d_in[0], (const float*)d_in[1], (const float*)d_in[2],
        (const float*)d_in[3], (const float*)d_in[4], (const float*)d_in[5],
        (float*)d_out);
}

// round 17
// speedup vs baseline: 1.1575x; 1.1484x over previous
#include <cuda_runtime.h>
#include <cuda_bf16.h>
#include <math.h>

#define TT 1024
#define NB 256
#define DX 16
#define DU 16
#define DA 32
#define NT 256
#define CH 64
#define SLABS 8
#define CONV_EPS 2e-5f

__device__ __align__(16) float g_LpF[NB * 256];
__device__ __align__(16) float g_LtF[NB * 256];
__device__ __align__(16) float g_K[NB * 512];
__device__ float g_muc[NB * 16];
__device__ int g_tconv[NB];

// in-warp unrolled 16x16 Gauss-Jordan inverse (lane j owns column j&15).
__device__ __forceinline__ void inv16_warp(float Sc[DX], int lane)
{
    const unsigned FULL = 0xffffffffu;
    #pragma unroll
    for (int k = 0; k < DX; ++k) {
        float piv = __shfl_sync(FULL, Sc[k], k);
        float d   = __frcp_rn(piv);
        float rjj = (lane == k) ? d : Sc[k] * d;
        #pragma unroll
        for (int i = 0; i < DX; ++i) {
            if (i == k) continue;
            float cki  = __shfl_sync(FULL, Sc[i], k);
            float base = (lane == k) ? 0.f : Sc[i];
            Sc[i] = fmaf(-cki, rjj, base);
        }
        Sc[k] = rjj;
    }
}

// ==================== Phase A: exact Kalman steps until freeze ====================
__global__ __launch_bounds__(NT, 2)
void ldm_phaseA(const float* __restrict__ a_g,
                const float* __restrict__ u_g,
                const float* __restrict__ mask_g,
                const float* __restrict__ A_g,
                const float* __restrict__ B_g,
                const float* __restrict__ C_g,
                const float* __restrict__ mu0_g,
                const float* __restrict__ Lam0_g,
                const float* __restrict__ Wl_g,
                const float* __restrict__ Rl_g,
                float* __restrict__ out)
{
    const int b   = blockIdx.x;
    const int tid = threadIdx.x;

    float* mu_pred_out = out;
    float* mu_t_out    = out + (size_t)TT * NB * DX;
    float* Lp_out      = out + (size_t)2 * TT * NB * DX;
    float* Lt_out      = Lp_out + (size_t)TT * NB * 256;

    __shared__ float Cs[DA * 17];
    __shared__ float Ct2[DX * 33];
    __shared__ float As[DX * 17];
    __shared__ float Bs[DX * 17];
    __shared__ float Us[DX * 17];
    __shared__ float Pbuf[2][DX * 17];
    __shared__ float LTs[DX * 17];
    __shared__ float ALs[DX * 17];
    __shared__ float TIs[DX * 17];
    __shared__ float Vs[DX * 17];
    __shared__ float Wd[DX], Rd[DA];
    __shared__ float sa[2][DA], su[2][DU], smv2[2];
    __shared__ float rr[DA], cr[DX];
    __shared__ float muS[2][DX], mut[DX];
    __shared__ float wmax8[NT / 32];
    __shared__ int   lastChange, convFlag;

    for (int i = tid; i < DA * DX; i += NT) Cs[(i / DX) * 17 + (i % DX)] = C_g[i];
    for (int i = tid; i < DX * DX; i += NT) {
        As[(i / DX) * 17 + (i % DX)]      = A_g[i];
        Pbuf[0][(i / DX) * 17 + (i % DX)] = Lam0_g[i];
    }
    for (int i = tid; i < DX * DU; i += NT) Bs[(i / DU) * 17 + (i % DU)] = B_g[i];
    if (tid < DX) { Wd[tid] = expf(Wl_g[tid]); muS[0][tid] = mu0_g[tid]; }
    if (tid < DA) Rd[tid] = expf(Rl_g[tid]);
    if (tid == 0) { lastChange = 0; convFlag = 0; }
    __syncthreads();

    for (int i = tid; i < DX * DA; i += NT) {
        int x = i >> 5, aa = i & 31;
        Ct2[x * 33 + aa] = Cs[aa * 17 + x] / Rd[aa];
    }
    {
        int lc = 0;
        for (int t = tid + 1; t < TT; t += NT)
            if (mask_g[(size_t)b * TT + t] != mask_g[(size_t)b * TT + t - 1]) lc = t;
        atomicMax(&lastChange, lc);
    }
    __syncthreads();

    const int x16 = tid >> 4, y16 = tid & 15;
    const int lane = tid & 31, wid = tid >> 5;
    const int lj   = lane & 15;

    {
        float s = 0.f;
        #pragma unroll
        for (int aa = 0; aa < DA; ++aa) s += Ct2[x16 * 33 + aa] * Cs[aa * 17 + y16];
        Us[x16 * 17 + y16] = s;
    }
    if (tid < DA) sa[0][tid] = a_g[(size_t)b * TT * DA + tid];
    if (tid >= 64 && tid < 64 + DU) su[0][tid - 64] = u_g[(size_t)b * TT * DU + (tid - 64)];
    if (tid == 96) smv2[0] = mask_g[(size_t)b * TT];
    if (tid >= 128 && tid < 128 + DA) {
        int aa = tid - 128;
        float s = 0.f;
        #pragma unroll
        for (int y = 0; y < DX; ++y) s += Cs[aa * 17 + y] * muS[0][y];
        rr[aa] = s;
    }
    __syncthreads();

    float Uic[DX];
    if (wid == 0) {
        #pragma unroll
        for (int i = 0; i < DX; ++i) Uic[i] = Us[i * 17 + lj];
        inv16_warp(Uic, lj);
    }

    float* Pcur  = Pbuf[0];
    float* Pnext = Pbuf[1];
    int tconv = TT;
    float mfreeze = 1.f;

    #pragma unroll 1
    for (int t = 0; t < TT; ++t) {
        const int p = t & 1;
        const float m = smv2[p];
        const bool doUpd = (m != 0.0f);

        if (doUpd && wid == 0) {
            float Tc[DX];
            #pragma unroll
            for (int i = 0; i < DX; ++i) Tc[i] = Pcur[i * 17 + lj] + Uic[i];
            inv16_warp(Tc, lj);
            if (lane < DX) {
                #pragma unroll
                for (int i = 0; i < DX; ++i) TIs[i * 17 + lj] = Tc[i];
            }
        }
        if (doUpd && tid >= 64 && tid < 64 + DX) {
            int x = tid - 64;
            float s = 0.f;
            #pragma unroll
            for (int aa = 0; aa < DA; ++aa)
                s += Ct2[x * 33 + aa] * (m * sa[p][aa] - rr[aa]);
            cr[x] = s;
        }
        if (t + 1 < TT) {
            const size_t base = (size_t)b * TT + t + 1;
            if (tid >= 192 && tid < 192 + DA) sa[1 - p][tid - 192] = a_g[base * DA + tid - 192];
            if (tid >= 224 && tid < 224 + DU)
                su[1 - p][tid - 224] = (t + 1 == TT - 1) ? 0.f : u_g[base * DU + tid - 224];
            if (tid == 240) smv2[1 - p] = mask_g[base];
        }
        __syncthreads();

        if (doUpd) {
            float s = 0.f;
            #pragma unroll
            for (int z = 0; z < DX; ++z) s += TIs[x16 * 17 + z] * Pcur[z * 17 + y16];
            Vs[x16 * 17 + y16] = s;
        }
        __syncthreads();

        {
            float s = Pcur[x16 * 17 + y16];
            if (doUpd) {
                #pragma unroll
                for (int z = 0; z < DX; ++z) s -= Pcur[x16 * 17 + z] * Vs[z * 17 + y16];
            }
            LTs[x16 * 17 + y16] = s;
        }
        __syncthreads();

        {
            float s = 0.f;
            #pragma unroll
            for (int z = 0; z < DX; ++z) s += As[x16 * 17 + z] * LTs[z * 17 + y16];
            ALs[x16 * 17 + y16] = s;
        }
        if (tid < DX) {
            float s = muS[p][tid];
            if (doUpd) {
                float acc = 0.f;
                #pragma unroll
                for (int j = 0; j < DX; ++j) acc += LTs[tid * 17 + j] * cr[j];
                s = fmaf(m, acc, s);
            }
            mut[tid] = s;
        }
        __syncthreads();

        float mydiff;
        {
            float s = (x16 == y16) ? Wd[x16] : 0.f;
            #pragma unroll
            for (int z = 0; z < DX; ++z) s += ALs[x16 * 17 + z] * As[y16 * 17 + z];
            Pnext[x16 * 17 + y16] = s;
            mydiff = fabsf(s - Pcur[x16 * 17 + y16]);
        }
        #pragma unroll
        for (int o = 16; o; o >>= 1)
            mydiff = fmaxf(mydiff, __shfl_xor_sync(0xffffffffu, mydiff, o));
        if (lane == 0) wmax8[wid] = mydiff;
        if (tid < DX) {
            float s = 0.f;
            #pragma unroll
            for (int y = 0; y < DX; ++y) s += As[tid * 17 + y] * mut[y];
            #pragma unroll
            for (int uu = 0; uu < DU; ++uu) s += Bs[tid * 17 + uu] * su[p][uu];
            muS[1 - p][tid] = s;
        }
        __syncthreads();

        {
            size_t ob = (size_t)t * NB + b;
            Lp_out[ob * 256 + tid] = Pnext[x16 * 17 + y16];
            Lt_out[ob * 256 + tid] = LTs[x16 * 17 + y16];
            if (tid < DX) mu_t_out[ob * DX + tid] = mut[tid];
            else if (tid < 2 * DX) mu_pred_out[ob * DX + tid - DX] = muS[1 - p][tid - DX];
        }
        if (tid >= 128 && tid < 128 + DA) {
            int aa = tid - 128;
            float s = 0.f;
            #pragma unroll
            for (int y = 0; y < DX; ++y) s += Cs[aa * 17 + y] * muS[1 - p][y];
            rr[aa] = s;
        }
        if (tid == 255) {
            float md = wmax8[0];
            #pragma unroll
            for (int w = 1; w < NT / 32; ++w) md = fmaxf(md, wmax8[w]);
            convFlag = (md < CONV_EPS && t >= lastChange &&
                        (t + 1) < TT && (((t + 1) & 3) == 0)) ? 1 : 0;
        }
        __syncthreads();

        { float* tp = Pcur; Pcur = Pnext; Pnext = tp; }
        if (convFlag) { tconv = t + 1; mfreeze = m; break; }
    }

    if (tid == 0) g_tconv[b] = tconv;
    if (tconv >= TT) return;

    g_LpF[b * 256 + tid] = Pcur[x16 * 17 + y16];
    g_LtF[b * 256 + tid] = LTs[x16 * 17 + y16];
    #pragma unroll
    for (int q = 0; q < 2; ++q) {
        int e = tid + q * NT, x = e >> 5, aa = e & 31;
        float s = 0.f;
        #pragma unroll
        for (int y = 0; y < DX; ++y) s += LTs[x * 17 + y] * Ct2[y * 33 + aa];
        g_K[b * 512 + x * 32 + aa] = mfreeze * s;
    }
    if (tid < DX) g_muc[b * 16 + tid] = muS[tconv & 1][tid];
}

// ==================== tail: Lambda fill (y>=1) + mu Phase B (y==0), overlapped ====
// Natural register allocation (R11-best config). Fill branch unrolled 4x.
__global__ __launch_bounds__(NT)
void ldm_tail(const float* __restrict__ a_g,
              const float* __restrict__ u_g,
              const float* __restrict__ mask_g,
              const float* __restrict__ A_g,
              const float* __restrict__ B_g,
              const float* __restrict__ C_g,
              float* __restrict__ out)
{
    const int b = blockIdx.x, tid = threadIdx.x;
    float* mu_pred_out = out;
    float* mu_t_out    = out + (size_t)TT * NB * DX;
    float* Lp_out      = out + (size_t)2 * TT * NB * DX;
    float* Lt_out      = Lp_out + (size_t)TT * NB * 256;

    if (blockIdx.y > 0) {
        // ---------------- Lambda fill slab: 4x-unrolled independent stores ----
        const int slab = blockIdx.y - 1;
        const int tb0 = slab * (TT / SLABS);
        const int tb1 = tb0 + (TT / SLABS);
        const int tc  = g_tconv[b];
        const int ts  = tc > tb0 ? tc : tb0;
        if (ts >= tb1) return;

        const int r   = tid & 127;
        const int rr2 = r & 63;
        const float4 val = (r < 64) ? ((const float4*)g_LpF)[b * 64 + rr2]
                                    : ((const float4*)g_LtF)[b * 64 + rr2];
        float4* dst = (float4*)((r < 64) ? Lp_out : Lt_out);

        for (int t = ts + (tid >> 7); t < tb1; t += 8) {
            #pragma unroll
            for (int k = 0; k < 4; ++k) {
                int tt = t + 2 * k;
                if (tt < tb1)
                    dst[((size_t)tt * NB + b) * 64 + rr2] = val;
            }
        }
        return;
    }

    // ---------------- Phase B: frozen-gain mu recurrence ----------------
    const int tconv = g_tconv[b];
    if (tconv >= TT) return;

    __shared__ float As[DX * 17], Bs[DX * 17], Cs[DA * 17], Ks[DX * 33];
    __shared__ float FM[DX * 17], MM[DX * 17], M2s[DX * 17], M3s[DX * 17], M4s[DX * 17];
    __shared__ __align__(16) float AB[CH * DA];
    __shared__ __align__(16) float UB[CH * DU];
    __shared__ float GB[CH * 17], HB[CH * 17];
    __shared__ float S1[(CH / 4) * 17], S2[(CH / 4) * 17], HH[(CH / 4) * 17];
    __shared__ float CHK[(CH / 4 + 1) * 17];
    __shared__ float PBF[CH * 17];
    __shared__ float MB[CH];

    const int x16 = tid >> 4, y16 = tid & 15;
    const int lane = tid & 31, wid = tid >> 5;

    for (int i = tid; i < DA * DX; i += NT) Cs[(i / DX) * 17 + (i % DX)] = C_g[i];
    for (int i = tid; i < DX * DX; i += NT) As[(i / DX) * 17 + (i % DX)] = A_g[i];
    for (int i = tid; i < DX * DU; i += NT) Bs[(i / DU) * 17 + (i % DU)] = B_g[i];
    #pragma unroll
    for (int q = 0; q < 2; ++q) {
        int e = tid + q * NT;
        Ks[(e >> 5) * 33 + (e & 31)] = g_K[b * 512 + e];
    }
    __syncthreads();

    {
        float s = (x16 == y16) ? 1.f : 0.f;
        #pragma unroll
        for (int aa = 0; aa < DA; ++aa) s -= Ks[x16 * 33 + aa] * Cs[aa * 17 + y16];
        FM[x16 * 17 + y16] = s;
    }
    __syncthreads();
    {
        float s = 0.f;
        #pragma unroll
        for (int z = 0; z < DX; ++z) s += As[x16 * 17 + z] * FM[z * 17 + y16];
        MM[x16 * 17 + y16] = s;
    }
    __syncthreads();
    {
        float s = 0.f;
        #pragma unroll
        for (int z = 0; z < DX; ++z) s += MM[x16 * 17 + z] * MM[z * 17 + y16];
        M2s[x16 * 17 + y16] = s;
    }
    __syncthreads();
    {
        float s3 = 0.f, s4 = 0.f;
        #pragma unroll
        for (int z = 0; z < DX; ++z) {
            s3 += M2s[x16 * 17 + z] * MM[z * 17 + y16];
            s4 += M2s[x16 * 17 + z] * M2s[z * 17 + y16];
        }
        M3s[x16 * 17 + y16] = s3;
        M4s[x16 * 17 + y16] = s4;
    }
    __syncthreads();

    float M4row[DX], muv = 0.f;
    if (wid == 0) {
        if (lane < DX) {
            #pragma unroll
            for (int j = 0; j < DX; ++j) M4row[j] = M4s[lane * 17 + j];
            muv = g_muc[b * 16 + lane];
        } else {
            #pragma unroll
            for (int j = 0; j < DX; ++j) M4row[j] = 0.f;
        }
    }

    for (int t0 = tconv; t0 < TT; t0 += CH) {
        const int L   = min(CH, TT - t0);
        const int NGl = L >> 2;

        {
            const float4* a4 = (const float4*)(a_g + ((size_t)b * TT + t0) * DA);
            for (int i2 = tid; i2 < L * 8; i2 += NT) ((float4*)AB)[i2] = a4[i2];
            const float4* u4 = (const float4*)(u_g + ((size_t)b * TT + t0) * DU);
            for (int i2 = tid; i2 < L * 4; i2 += NT) ((float4*)UB)[i2] = u4[i2];
            if (tid < L) MB[tid] = mask_g[(size_t)b * TT + t0 + tid];
        }
        __syncthreads();

        for (int e = tid; e < L * DX; e += NT) {
            int s = e >> 4, x = e & 15;
            const float* ar = AB + s * DA;
            float g = 0.f;
            #pragma unroll
            for (int aa = 0; aa < DA; ++aa) g += Ks[x * 33 + aa] * ar[aa];
            GB[s * 17 + x] = MB[s] * g;
        }
        __syncthreads();

        for (int e = tid; e < L * DX; e += NT) {
            int s = e >> 4, x = e & 15;
            float h = 0.f;
            #pragma unroll
            for (int z = 0; z < DX; ++z) h += As[x * 17 + z] * GB[s * 17 + z];
            if (t0 + s != TT - 1) {
                const float* ur = UB + s * DU;
                #pragma unroll
                for (int uu = 0; uu < DU; ++uu) h += Bs[x * 17 + uu] * ur[uu];
            }
            HB[s * 17 + x] = h;
        }
        __syncthreads();

        for (int e = tid; e < NGl * DX; e += NT) {
            int q = e >> 4, x = e & 15;
            const float* h0 = HB + (4 * q) * 17;
            float s1 = h0[17 + x], s2 = h0[34 + x], hh = h0[51 + x];
            #pragma unroll
            for (int j = 0; j < DX; ++j) {
                float h0j = h0[j], h1j = h0[17 + j], h2j = h0[34 + j];
                float mj  = MM[x * 17 + j];
                float m2j = M2s[x * 17 + j];
                s1 = fmaf(mj,  h0j, s1);
                s2 = fmaf(m2j, h0j, fmaf(mj, h1j, s2));
                hh = fmaf(M3s[x * 17 + j], h0j, fmaf(m2j, h1j, fmaf(mj, h2j, hh)));
            }
            S1[q * 17 + x] = s1;
            S2[q * 17 + x] = s2;
            HH[q * 17 + x] = hh;
        }
        __syncthreads();

        if (wid == 0) {
            #pragma unroll 1
            for (int q = 0; q < NGl; ++q) {
                float nm = (lane < DX) ? HH[q * 17 + lane] : 0.f;
                if (lane < DX) CHK[q * 17 + lane] = muv;
                float a0 = nm, a1 = 0.f;
                #pragma unroll
                for (int j = 0; j < DX; j += 2) {
                    float m0 = __shfl_sync(0xffffffffu, muv, j);
                    float m1 = __shfl_sync(0xffffffffu, muv, j + 1);
                    a0 = fmaf(M4row[j],     m0, a0);
                    a1 = fmaf(M4row[j + 1], m1, a1);
                }
                muv = a0 + a1;
            }
            if (lane < DX) CHK[NGl * 17 + lane] = muv;
        }
        __syncthreads();

        for (int e = tid; e < L * DX; e += NT) {
            int s = e >> 4, x = e & 15, q = s >> 2, r = s & 3;
            float pv;
            if (r == 0) {
                pv = CHK[q * 17 + x];
            } else {
                const float* Mr = (r == 1) ? MM : (r == 2) ? M2s : M3s;
                pv = (r == 1) ? HB[(4 * q) * 17 + x]
                   : (r == 2) ? S1[q * 17 + x] : S2[q * 17 + x];
                #pragma unroll
                for (int j = 0; j < DX; ++j) pv = fmaf(Mr[x * 17 + j], CHK[q * 17 + j], pv);
            }
            PBF[s * 17 + x] = pv;
        }
        __syncthreads();

        for (int e = tid; e < L * DX; e += NT) {
            int s = e >> 4, x = e & 15;
            int t = t0 + s;
            float mt = GB[s * 17 + x];
            #pragma unroll
            for (int j = 0; j < DX; ++j) mt = fmaf(FM[x * 17 + j], PBF[s * 17 + j], mt);
            float mpn = (s + 1 < L) ? PBF[(s + 1) * 17 + x] : CHK[NGl * 17 + x];
            size_t ob = (size_t)t * NB + b;
            mu_t_out[ob * DX + x]    = mt;
            mu_pred_out[ob * DX + x] = mpn;
        }
        __syncthreads();
    }
}

extern "C" void kernel_launch(void* const* d_in, const int* in_sizes, int n_in,
                              void* d_out, int out_size)
{
    (void)in_sizes; (void)n_in; (void)out_size;
    ldm_phaseA<<<NB, NT>>>(
        (const float*)d_in[0], (const float*)d_in[1], (const float*)d_in[2],
        (const float*)d_in[3], (const float*)d_in[4], (const float*)d_in[5],
        (const float*)d_in[6], (const float*)d_in[7], (const float*)d_in[8],
        (const float*)d_in[9], (float*)d_out);
    ldm_tail<<<dim3(NB, SLABS + 1), NT>>>(
        (const float*)d_in[0], (const float*)d_in[1], (const float*)d_in[2],
        (const float*)d_in[3], (const float*)d_in[4], (const float*)d_in[5],
        (float*)d_out);
}